// round 1
// baseline (speedup 1.0000x reference)
#include <cuda_runtime.h>
#include <cstdint>

#define S 64
#define SCALE 8
#define PATCH 56
#define IMG 448
#define MAXB 32

// Scratch: for each param-batch b (0..B-1), src_block_of_dst_block[l] = k
// such that permutation M[k,l] == 1.
__device__ int g_src[MAXB][S];

__device__ __forceinline__ float neg_inf() { return __int_as_float(0xff800000); }

// One block per batch matrix, 64 threads (thread t owns column t).
__global__ void __launch_bounds__(64) perm_kernel(
    const float* __restrict__ params,
    const int* __restrict__ bseq,
    const int* __restrict__ bsz,
    float* __restrict__ result_out,   // d_out + B*3*448*448
    int B)
{
    __shared__ float rcm[S * S];
    __shared__ float cmax[S];
    __shared__ int   cargr[S];
    __shared__ unsigned char rowm[S], colm[S];
    __shared__ int rowofcol[S];
    __shared__ float wval[2];
    __shared__ int   widx[2];
    __shared__ int   s_win;

    const int t = threadIdx.x;
    const int lane = t & 31;
    const int warp = t >> 5;
    const int b = blockIdx.x;

    const int start = bseq[0] * bsz[0];
    const float* p = params + (size_t)(start + b) * (S * S);

    // Load (coalesced over t)
    #pragma unroll 4
    for (int i = 0; i < S; i++) rcm[i * S + t] = p[i * S + t];
    rowm[t] = 0; colm[t] = 0;
    __syncthreads();

    // Column-wise softmax (axis=0 of [S,S])
    float mx = neg_inf();
    #pragma unroll 4
    for (int i = 0; i < S; i++) mx = fmaxf(mx, rcm[i * S + t]);
    float sum = 0.f;
    #pragma unroll 4
    for (int i = 0; i < S; i++) {
        float e = expf(rcm[i * S + t] - mx);
        sum += e;
        rcm[i * S + t] = e;
    }
    float inv = 1.f / sum;
    float m0 = neg_inf(); int a0 = 0;
    #pragma unroll 4
    for (int i = 0; i < S; i++) {
        float v = rcm[i * S + t] * inv;
        rcm[i * S + t] = v;
        if (v > m0) { m0 = v; a0 = i; }
    }
    cmax[t] = m0; cargr[t] = a0;
    __syncthreads();

    // Greedy assignment: 64x (global argmax over unmasked rows/cols; mask)
    for (int step = 0; step < S; step++) {
        float v = colm[t] ? neg_inf() : cmax[t];
        int idx = cargr[t] * S + t;       // linear index r*64+c for tie-break
        #pragma unroll
        for (int off = 16; off; off >>= 1) {
            float v2 = __shfl_down_sync(0xffffffffu, v, off);
            int   i2 = __shfl_down_sync(0xffffffffu, idx, off);
            if (v2 > v || (v2 == v && i2 < idx)) { v = v2; idx = i2; }
        }
        if (lane == 0) { wval[warp] = v; widx[warp] = idx; }
        __syncthreads();
        if (t == 0) {
            float va = wval[0], vb = wval[1];
            int ia = widx[0], ib = widx[1];
            s_win = (vb > va || (vb == va && ib < ia)) ? ib : ia;
        }
        __syncthreads();
        const int win = s_win;
        const int r = win >> 6;
        const int c = win & 63;
        if (t == 0) rowofcol[c] = r;
        if (t == c) colm[t] = 1;
        if (t == r) rowm[t] = 1;
        __syncthreads();
        // Columns whose tracked argmax row just got masked: rescan
        if (!colm[t] && cargr[t] == r) {
            float m = neg_inf(); int ai = 0;
            #pragma unroll 4
            for (int i = 0; i < S; i++) {
                float val = rcm[i * S + t];
                if (!rowm[i] && val > m) { m = val; ai = i; }
            }
            cmax[t] = m; cargr[t] = ai;
        }
        __syncthreads();
    }

    g_src[b][t] = rowofcol[t];

    // Write result region for OUTPUT batch bo = B-1-b (the [::-1] flip),
    // broadcast over 3 channels: result[bo,ch,k,l] = (k == rowofcol[l])
    const int bo = B - 1 - b;
    float* dst = result_out + (size_t)bo * 3 * S * S;
    const int rc = rowofcol[t];
    #pragma unroll
    for (int ch = 0; ch < 3; ch++) {
        #pragma unroll 4
        for (int k = 0; k < S; k++) {
            dst[ch * S * S + k * S + t] = (k == rc) ? 1.0f : 0.0f;
        }
    }
}

// One block per (b, c, dest-block l) tile: gather-copy 56x56 floats.
__global__ void __launch_bounds__(256) scatter_kernel(
    const float* __restrict__ x,
    float* __restrict__ out,
    int B)
{
    const int tile = blockIdx.x;
    const int l  = tile & 63;
    const int bc = tile >> 6;       // b*3 + c
    const int b  = bc / 3;

    const int k  = g_src[B - 1 - b][l];   // source block for this dest block
    const int t1 = l >> 3, t2 = l & 7;
    const int s1 = k >> 3, s2 = k & 7;

    const float4* __restrict__ src =
        (const float4*)(x + ((size_t)bc * IMG + (size_t)s1 * PATCH) * IMG + (size_t)s2 * PATCH);
    float4* __restrict__ dst =
        (float4*)(out + ((size_t)bc * IMG + (size_t)t1 * PATCH) * IMG + (size_t)t2 * PATCH);

    // 56 rows x 14 float4 per row; image row stride = 448 floats = 112 float4
    for (int i = threadIdx.x; i < PATCH * (PATCH / 4); i += blockDim.x) {
        const int row = i / 14;
        const int c4  = i - row * 14;
        dst[row * 112 + c4] = src[row * 112 + c4];
    }
}

extern "C" void kernel_launch(void* const* d_in, const int* in_sizes, int n_in,
                              void* d_out, int out_size)
{
    const float* x      = (const float*)d_in[0];
    const float* params = (const float*)d_in[1];
    const int*   bseq   = (const int*)d_in[2];
    const int*   bsz    = (const int*)d_in[3];
    float* out = (float*)d_out;

    const int B = in_sizes[0] / (3 * IMG * IMG);          // 32
    float* result_out = out + (size_t)in_sizes[0];        // out part first, then result

    perm_kernel<<<B, 64>>>(params, bseq, bsz, result_out, B);
    scatter_kernel<<<B * 3 * S, 256>>>(x, out, B);
}

// round 4
// speedup vs baseline: 1.1835x; 1.1835x over previous
#include <cuda_runtime.h>
#include <cstdint>

#define S 64
#define SCALE 8
#define PATCH 56
#define IMG 448
#define MAXB 32

// Scratch: for each param-batch b, src_block_of_dst_block[l] = k (M[k,l] == 1).
__device__ int g_src[MAXB][S];

__device__ __forceinline__ float neg_inf() { return __int_as_float(0xff800000); }

// One WARP per batch matrix. Lane t owns columns t and t+32.
__global__ void __launch_bounds__(32) perm_kernel(
    const float* __restrict__ params,
    const int* __restrict__ bseq,
    const int* __restrict__ bsz,
    float* __restrict__ result_out,   // d_out + B*3*448*448
    int B)
{
    // Column-major, padded: rcm[c][i], bank = (65*c + i) % 32 = (c+i)%32 -> conflict-free
    __shared__ float rcm[S][S + 1];
    __shared__ float mat[S][S];       // final 0/1 matrix, aligned for float4 copy-out

    const int t = threadIdx.x;
    const int b = blockIdx.x;

    const int start = bseq[0] * bsz[0];
    const float* __restrict__ p = params + (size_t)(start + b) * (S * S);

    // Load transposed (global reads coalesced over lanes)
    #pragma unroll 8
    for (int i = 0; i < S; i++) {
        rcm[t][i]      = p[i * S + t];
        rcm[t + 32][i] = p[i * S + t + 32];
    }
    __syncwarp();

    // Per-column softmax (axis 0), track running argmax
    float cv[2]; int ca[2];
    #pragma unroll
    for (int h = 0; h < 2; h++) {
        const int c = t + 32 * h;
        float mx = neg_inf();
        #pragma unroll 8
        for (int i = 0; i < S; i++) mx = fmaxf(mx, rcm[c][i]);
        float sum = 0.f;
        #pragma unroll 8
        for (int i = 0; i < S; i++) {
            float e = expf(rcm[c][i] - mx);   // accurate expf: argmax safety
            sum += e;
            rcm[c][i] = e;
        }
        const float inv = 1.f / sum;
        float m = neg_inf(); int a = 0;
        #pragma unroll 8
        for (int i = 0; i < S; i++) {
            float v = rcm[c][i] * inv;
            rcm[c][i] = v;
            if (v > m) { m = v; a = i; }
        }
        cv[h] = m; ca[h] = a;
    }
    __syncwarp();

    int arow[2] = { -1, -1 };   // assigned source row for my 2 columns
    bool done[2] = { false, false };

    #pragma unroll 1
    for (int step = 0; step < S; step++) {
        // Local best of my 2 columns (tie -> smaller linear idx r*64+c)
        float v0 = done[0] ? neg_inf() : cv[0];
        float v1 = done[1] ? neg_inf() : cv[1];
        int i0 = ca[0] * S + t;
        int i1 = ca[1] * S + t + 32;
        float v; int idx;
        if (v1 > v0 || (v1 == v0 && i1 < i0)) { v = v1; idx = i1; }
        else                                  { v = v0; idx = i0; }

        // Warp argmax butterfly: all lanes end with the global winner
        #pragma unroll
        for (int off = 16; off; off >>= 1) {
            float v2 = __shfl_xor_sync(0xffffffffu, v, off);
            int   i2 = __shfl_xor_sync(0xffffffffu, idx, off);
            if (v2 > v || (v2 == v && i2 < idx)) { v = v2; idx = i2; }
        }
        const int r = idx >> 6;
        const int c = idx & 63;

        if (c == t)      { arow[0] = r; done[0] = true; }
        if (c == t + 32) { arow[1] = r; done[1] = true; }

        // Mask row r everywhere: -inf write, conflict-free across lanes
        rcm[t][r]      = neg_inf();
        rcm[t + 32][r] = neg_inf();
        __syncwarp();

        // Rescan columns whose tracked argmax just died (masked rows are -inf)
        #pragma unroll
        for (int h = 0; h < 2; h++) {
            if (!done[h] && ca[h] == r) {
                const int cc = t + 32 * h;
                float m = neg_inf(); int a = 0;
                #pragma unroll 8
                for (int i = 0; i < S; i++) {
                    float val = rcm[cc][i];
                    if (val > m) { m = val; a = i; }
                }
                cv[h] = m; ca[h] = a;
            }
        }
        __syncwarp();
    }

    g_src[b][t]      = arow[0];
    g_src[b][t + 32] = arow[1];

    // Build 0/1 matrix once in smem, then float4-blast 3 channel copies
    #pragma unroll 8
    for (int k = 0; k < S; k++) {
        mat[k][t]      = (k == arow[0]) ? 1.0f : 0.0f;
        mat[k][t + 32] = (k == arow[1]) ? 1.0f : 0.0f;
    }
    __syncwarp();

    const int bo = B - 1 - b;                       // [::-1] batch flip
    float* __restrict__ dst = result_out + (size_t)bo * 3 * S * S;
    const float4* __restrict__ msrc = (const float4*)&mat[0][0];
    #pragma unroll
    for (int j = 0; j < (S * S) / (4 * 32); j++) {  // 32 float4 per lane
        const int i = j * 32 + t;
        float4 val = msrc[i];
        ((float4*)dst)[i]                 = val;
        ((float4*)dst)[i + S * S / 4]     = val;
        ((float4*)dst)[i + 2 * S * S / 4] = val;
    }
}

// One block per (b, c, dest-block l) tile: gather-copy 56x56 floats.
// (identical to the R1-passing scatter kernel)
__global__ void __launch_bounds__(256) scatter_kernel(
    const float* __restrict__ x,
    float* __restrict__ out,
    int B)
{
    const int tile = blockIdx.x;
    const int l  = tile & 63;
    const int bc = tile >> 6;       // b*3 + c
    const int b  = bc / 3;

    const int k  = g_src[B - 1 - b][l];   // source block for this dest block
    const int t1 = l >> 3, t2 = l & 7;
    const int s1 = k >> 3, s2 = k & 7;

    const float4* __restrict__ src =
        (const float4*)(x + ((size_t)bc * IMG + (size_t)s1 * PATCH) * IMG + (size_t)s2 * PATCH);
    float4* __restrict__ dst =
        (float4*)(out + ((size_t)bc * IMG + (size_t)t1 * PATCH) * IMG + (size_t)t2 * PATCH);

    // 56 rows x 14 float4 per row; image row stride = 448 floats = 112 float4
    for (int i = threadIdx.x; i < PATCH * (PATCH / 4); i += blockDim.x) {
        const int row = i / 14;
        const int c4  = i - row * 14;
        dst[row * 112 + c4] = src[row * 112 + c4];
    }
}

extern "C" void kernel_launch(void* const* d_in, const int* in_sizes, int n_in,
                              void* d_out, int out_size)
{
    const float* x      = (const float*)d_in[0];
    const float* params = (const float*)d_in[1];
    const int*   bseq   = (const int*)d_in[2];
    const int*   bsz    = (const int*)d_in[3];
    float* out = (float*)d_out;

    const int B = in_sizes[0] / (3 * IMG * IMG);          // 32
    float* result_out = out + (size_t)in_sizes[0];        // x-part first, then result

    perm_kernel<<<B, 32>>>(params, bseq, bsz, result_out, B);
    scatter_kernel<<<B * 3 * S, 256>>>(x, out, B);
}

// round 6
// speedup vs baseline: 1.3935x; 1.1774x over previous
#include <cuda_runtime.h>
#include <cstdint>

typedef unsigned long long ull;

#define S 64
#define SCALE 8
#define PATCH 56
#define IMG 448
#define MAXB 32
#define FULLMASK 0xffffffffu

// Scratch: for each param-batch b, src_block_of_dst_block[l] = k (M[k,l] == 1).
__device__ int g_src[MAXB][S];

__device__ __forceinline__ ull umax64(ull a, ull b) { return a > b ? a : b; }

// Max over 64 u64 keys at k[0..63] (masked entries are 0): 4 ILP chains.
__device__ __forceinline__ ull rescan64(const ull* __restrict__ k) {
    ull a = 0, b = 0, c = 0, d = 0;
    #pragma unroll
    for (int i = 0; i < 64; i += 4) {
        a = umax64(a, k[i]);
        b = umax64(b, k[i + 1]);
        c = umax64(c, k[i + 2]);
        d = umax64(d, k[i + 3]);
    }
    return umax64(umax64(a, b), umax64(c, d));
}

// One WARP per batch matrix. Lane t owns columns t and t+32 (lane-private!).
// key = (float_bits(value) << 12) | (4095 - (row*64 + col)); masked/done -> 0.
__global__ void __launch_bounds__(32) perm_kernel(
    const float* __restrict__ params,
    const int* __restrict__ bseq,
    const int* __restrict__ bsz,
    float* __restrict__ result_out,   // d_out + B*3*448*448
    int B)
{
    __shared__ ull sk[S][S + 2];      // keys, column-major-ish; 33.8 KB

    const int t = threadIdx.x;
    const int b = blockIdx.x;

    const int start = bseq[0] * bsz[0];
    const float* __restrict__ p = params + (size_t)(start + b) * (S * S);

    // Stage raw column values as floats INSIDE the key array (per-lane region).
    // Column c's float staging: fs + c*132 + i  (fs = sk viewed as float).
    float* __restrict__ fs = (float*)&sk[0][0];
    const int  stride_f = (S + 2) * 2;            // 132 floats per column slot

    #pragma unroll 8
    for (int i = 0; i < S; i++) {                 // coalesced over lanes per i
        fs[t * stride_f + i]        = p[i * S + t];
        fs[(t + 32) * stride_f + i] = p[i * S + t + 32];
    }
    // No sync needed: columns are lane-private throughout.

    ull head[2] = { 0, 0 };
    #pragma unroll
    for (int h = 0; h < 2; h++) {
        const int c = t + 32 * h;
        float* __restrict__ col = fs + c * stride_f;

        // Pass 1: max;  Pass 2: exp + sum (in place, float)
        float mx = col[0];
        #pragma unroll 8
        for (int i = 1; i < S; i++) mx = fmaxf(mx, col[i]);
        float sum = 0.f;
        #pragma unroll 8
        for (int i = 0; i < S; i++) {
            float e = expf(col[i] - mx);          // accurate expf: argmax safety
            sum += e;
            col[i] = e;
        }
        const float inv = 1.f / sum;

        // Pass 3 (DESCENDING i): float e -> u64 key, in place.
        // ull slot i overlaps float slots 2i,2i+1, consumed at earlier (larger)
        // descending steps -> clobber-free.
        ull* __restrict__ kcol = &sk[c][0];
        ull hk = 0;
        #pragma unroll 8
        for (int i = S - 1; i >= 0; i--) {
            float v = col[i] * inv;
            ull key = ((ull)__float_as_uint(v) << 12) | (ull)(4095 - (i * S + c));
            kcol[i] = key;
            hk = umax64(hk, key);
        }
        head[h] = hk;
    }

    int arow0 = -1, arow1 = -1;

    #pragma unroll 1
    for (int step = 0; step < S; step++) {
        // Phase 1: warp max of value bits (REDUX hardware reduction).
        const unsigned b0 = (unsigned)(head[0] >> 12);
        const unsigned b1 = (unsigned)(head[1] >> 12);
        const unsigned vmax = __reduce_max_sync(FULLMASK, b0 > b1 ? b0 : b1);

        // Phase 2: among ties on value bits, max of (4095 - flat_idx)
        //          -> smallest flat index, matching reference tie-break.
        unsigned cand = 0;
        if (b0 == vmax) cand = (unsigned)(head[0] & 4095u);
        if (b1 == vmax) { unsigned q = (unsigned)(head[1] & 4095u); if (q > cand) cand = q; }
        const unsigned im = __reduce_max_sync(FULLMASK, cand);
        const int idx = 4095 - (int)im;
        const int r = idx >> 6;
        const int c = idx & 63;

        // Ownership: winner column retires.
        if (c == t)           { arow0 = r; head[0] = 0; }
        else if (c == t + 32) { arow1 = r; head[1] = 0; }

        // Mask row r in my two (lane-private) columns.
        sk[t][r] = 0;
        sk[t + 32][r] = 0;

        // Rescan a column only if its tracked head row just died.
        if (head[0]) {
            const unsigned f0 = 4095u - (unsigned)(head[0] & 4095u);
            if ((int)(f0 >> 6) == r) head[0] = rescan64(&sk[t][0]);
        }
        if (head[1]) {
            const unsigned f1 = 4095u - (unsigned)(head[1] & 4095u);
            if ((int)(f1 >> 6) == r) head[1] = rescan64(&sk[t + 32][0]);
        }
    }

    g_src[b][t]      = arow0;
    g_src[b][t + 32] = arow1;

    // Reuse key smem as the 0/1 matrix (contiguous [64][64] floats).
    float* __restrict__ mat = (float*)&sk[0][0];
    #pragma unroll 8
    for (int k = 0; k < S; k++) {
        mat[k * S + t]      = (k == arow0) ? 1.0f : 0.0f;
        mat[k * S + t + 32] = (k == arow1) ? 1.0f : 0.0f;
    }
    __syncwarp();

    const int bo = B - 1 - b;                       // [::-1] batch flip
    float* __restrict__ dst = result_out + (size_t)bo * 3 * S * S;
    const float4* __restrict__ msrc = (const float4*)mat;
    #pragma unroll
    for (int j = 0; j < (S * S) / (4 * 32); j++) {  // 32 float4 per lane
        const int i = j * 32 + t;
        float4 val = msrc[i];
        ((float4*)dst)[i]                 = val;
        ((float4*)dst)[i + S * S / 4]     = val;
        ((float4*)dst)[i + 2 * S * S / 4] = val;
    }
}

// One block per (b, c, dest-block l) tile: gather-copy 56x56 floats.
// (identical to the measured 29.4us scatter kernel)
__global__ void __launch_bounds__(256) scatter_kernel(
    const float* __restrict__ x,
    float* __restrict__ out,
    int B)
{
    const int tile = blockIdx.x;
    const int l  = tile & 63;
    const int bc = tile >> 6;       // b*3 + c
    const int b  = bc / 3;

    const int k  = g_src[B - 1 - b][l];   // source block for this dest block
    const int t1 = l >> 3, t2 = l & 7;
    const int s1 = k >> 3, s2 = k & 7;

    const float4* __restrict__ src =
        (const float4*)(x + ((size_t)bc * IMG + (size_t)s1 * PATCH) * IMG + (size_t)s2 * PATCH);
    float4* __restrict__ dst =
        (float4*)(out + ((size_t)bc * IMG + (size_t)t1 * PATCH) * IMG + (size_t)t2 * PATCH);

    // 56 rows x 14 float4 per row; image row stride = 448 floats = 112 float4
    for (int i = threadIdx.x; i < PATCH * (PATCH / 4); i += blockDim.x) {
        const int row = i / 14;
        const int c4  = i - row * 14;
        dst[row * 112 + c4] = src[row * 112 + c4];
    }
}

extern "C" void kernel_launch(void* const* d_in, const int* in_sizes, int n_in,
                              void* d_out, int out_size)
{
    const float* x      = (const float*)d_in[0];
    const float* params = (const float*)d_in[1];
    const int*   bseq   = (const int*)d_in[2];
    const int*   bsz    = (const int*)d_in[3];
    float* out = (float*)d_out;

    const int B = in_sizes[0] / (3 * IMG * IMG);          // 32
    float* result_out = out + (size_t)in_sizes[0];        // x-part first, then result

    perm_kernel<<<B, 32>>>(params, bseq, bsz, result_out, B);
    scatter_kernel<<<B * 3 * S, 256>>>(x, out, B);
}